// round 13
// baseline (speedup 1.0000x reference)
#include <cuda_runtime.h>
#include <cuda_bf16.h>
#include <cfloat>
#include <cstdint>

// ---------------- problem constants ----------------
#define M_TOK   1024
#define KDIM    768
#define VOC     21128
#define VP      21248          // padded vocab: 166 * 128
#define NT2     166            // n-tiles of 128
#define BM      128
#define BN      128
#define BK      128            // fp8 elems per k-chunk = 128 bytes/row
#define NKT     6              // 768/128
#define NSTG    3
#define THETA   0.25f          // rescue threshold (~16 sigma of fp8 dot error)
#define WSCALE  16.0f          // W pre-scale before fp8 quant
#define INVSC   0.0625f        // 1/16 applied to acc in epilogue

// smem per stage: A 16K | B 16K
#define STG_BYTES 32768
#define R_B       16384
#define SM_TOTAL_G (NSTG * STG_BYTES)   // 98304 (epilogue reuses stage 0)

// ---------------- device scratch (allocation-free) ----------------
__device__ uint8_t g_Wq[(size_t)VP * KDIM];
__device__ uint8_t g_Aq[(size_t)M_TOK * KDIM];
__device__ float g_p1v[(size_t)M_TOK * NT2];
__device__ int   g_p1i[(size_t)M_TOK * NT2];
__device__ float g_p2v[(size_t)M_TOK * NT2];
__device__ int   g_p2i[(size_t)M_TOK * NT2];
__device__ float g_contrib[M_TOK];
__device__ int   g_mask_kind;

// ---------------- PTX helpers (portable, no 'a'-feature) ----------------
__device__ __forceinline__ uint32_t smem_u32(const void* p) {
    uint32_t a;
    asm("{ .reg .u64 t; cvta.to.shared.u64 t, %1; cvt.u32.u64 %0, t; }" : "=r"(a) : "l"(p));
    return a;
}
__device__ __forceinline__ void cp16(uint32_t dst, const void* src) {
    asm volatile("cp.async.cg.shared.global [%0], [%1], 16;" :: "r"(dst), "l"(src));
}
__device__ __forceinline__ void cp_commit() {
    asm volatile("cp.async.commit_group;" ::: "memory");
}
template <int N>
__device__ __forceinline__ void cp_wait() {
    asm volatile("cp.async.wait_group %0;" :: "n"(N) : "memory");
}
__device__ __forceinline__ void ldsm_x4(uint32_t* r, uint32_t addr) {
    asm volatile("ldmatrix.sync.aligned.m8n8.x4.shared.b16 {%0,%1,%2,%3}, [%4];"
                 : "=r"(r[0]), "=r"(r[1]), "=r"(r[2]), "=r"(r[3]) : "r"(addr));
}
// fp8 e4m3 MMA: m16n8k32, same fragment register counts as bf16 m16n8k16
__device__ __forceinline__ void mma_fp8(float* c, const uint32_t* a, const uint32_t* b) {
    asm volatile(
        "mma.sync.aligned.m16n8k32.row.col.f32.e4m3.e4m3.f32 "
        "{%0,%1,%2,%3}, {%4,%5,%6,%7}, {%8,%9}, {%0,%1,%2,%3};"
        : "+f"(c[0]), "+f"(c[1]), "+f"(c[2]), "+f"(c[3])
        : "r"(a[0]), "r"(a[1]), "r"(a[2]), "r"(a[3]), "r"(b[0]), "r"(b[1]));
}
__device__ __forceinline__ uint32_t sw128(uint32_t b) { return b ^ ((b >> 3) & 0x70); }

// pack 4 consecutive floats -> 4 e4m3 bytes (byte0 = x0). PTX cvt: first src -> upper half.
__device__ __forceinline__ uint32_t pack_e4m3_4(float x0, float x1, float x2, float x3) {
    uint16_t lo, hi;
    asm("cvt.rn.satfinite.e4m3x2.f32 %0, %1, %2;" : "=h"(lo) : "f"(x1), "f"(x0));
    asm("cvt.rn.satfinite.e4m3x2.f32 %0, %1, %2;" : "=h"(hi) : "f"(x3), "f"(x2));
    return (uint32_t)lo | ((uint32_t)hi << 16);
}

// top-2 merge keeping first-occurrence (min idx) semantics
__device__ __forceinline__ void top2_merge(float v, int i, float& m1, int& i1,
                                           float& m2, int& i2) {
    if (v > m1 || (v == m1 && i < i1)) {
        m2 = m1; i2 = i1; m1 = v; i1 = i;
    } else if (v > m2 || (v == m2 && i < i2)) {
        m2 = v; i2 = i;
    }
}

// ---------------- convert f32 -> fp8 (W scaled by 16) + fused mask probe ----------------
__global__ void convert_fp8(const float* __restrict__ A, const float* __restrict__ W,
                            const unsigned char* __restrict__ mb) {
    // block 0 also runs the mask-dtype probe
    if (blockIdx.x == 0) {
        __shared__ int nz[4];
        if (threadIdx.x < 4) nz[threadIdx.x] = 0;
        __syncthreads();
        int c[4] = {0, 0, 0, 0};
        for (int i = threadIdx.x; i < VOC; i += blockDim.x)
            if (mb[i]) c[i & 3]++;
        #pragma unroll
        for (int r = 0; r < 4; r++)
            if (c[r]) atomicAdd(&nz[r], c[r]);
        __syncthreads();
        if (threadIdx.x == 0) {
            int kind = 0;
            if (nz[0] > 0 && nz[1] == 0 && nz[2] == 0 && nz[3] == 0) kind = 1;
            else if (nz[0] == 0 && (nz[2] > 0 || nz[3] > 0))          kind = 2;
            g_mask_kind = kind;
        }
    }
    const size_t nW8 = (size_t)VP * KDIM / 8;
    const size_t nA8 = (size_t)M_TOK * KDIM / 8;
    const size_t nV8 = (size_t)VOC * KDIM / 8;
    for (size_t i = (size_t)blockIdx.x * blockDim.x + threadIdx.x;
         i < nW8 + nA8; i += (size_t)gridDim.x * blockDim.x) {
        uint2 out;
        if (i < nW8) {
            size_t e = i * 8;
            if (i < nV8) {
                float4 v0 = *(const float4*)(W + e);
                float4 v1 = *(const float4*)(W + e + 4);
                out.x = pack_e4m3_4(v0.x * WSCALE, v0.y * WSCALE, v0.z * WSCALE, v0.w * WSCALE);
                out.y = pack_e4m3_4(v1.x * WSCALE, v1.y * WSCALE, v1.z * WSCALE, v1.w * WSCALE);
            } else {
                out.x = 0u; out.y = 0u;
            }
            *(uint2*)(g_Wq + e) = out;
        } else {
            size_t e = (i - nW8) * 8;
            float4 v0 = *(const float4*)(A + e);
            float4 v1 = *(const float4*)(A + e + 4);
            out.x = pack_e4m3_4(v0.x, v0.y, v0.z, v0.w);
            out.y = pack_e4m3_4(v1.x, v1.y, v1.z, v1.w);
            *(uint2*)(g_Aq + e) = out;
        }
    }
}

// ---------------- stage loader: 128x128B A + 128x128B B (fp8) ----------------
__device__ __forceinline__ void load_stage(uint32_t sb, int buf, int m0, int n0,
                                           int kt, int tid) {
    uint32_t base = sb + buf * STG_BYTES;
    #pragma unroll
    for (int i = 0; i < 4; i++) {
        int id = tid + i * 256;                  // 0..1023
        int row = id >> 3, c = id & 7;           // 128 rows x 8 x 16B
        uint32_t so = sw128(row * 128 + c * 16);
        cp16(base + so,       g_Aq + (size_t)(m0 + row) * KDIM + kt + c * 16);
        cp16(base + R_B + so, g_Wq + (size_t)(n0 + row) * KDIM + kt + c * 16);
    }
}

// ---------------- stage compute: 4 x k32, 64 fp8-MMA per warp ----------------
__device__ __forceinline__ void compute_stage(uint32_t sb, int buf, int lane,
                                              int wm, int wn, float acc[4][4][4]) {
    uint32_t base = sb + buf * STG_BYTES;
    #pragma unroll
    for (int kk = 0; kk < 4; kk++) {
        uint32_t ah[4][4], bh[2][4];
        #pragma unroll
        for (int mi = 0; mi < 4; mi++) {
            int row = wm * 64 + mi * 16 + (lane & 15);
            uint32_t off = sw128(row * 128 + kk * 32 + ((lane >> 4) & 1) * 16);
            ldsm_x4(ah[mi], base + off);
        }
        #pragma unroll
        for (int bi = 0; bi < 2; bi++) {
            int row = wn * 32 + bi * 16 + (lane & 7) + ((lane >> 4) & 1) * 8;
            uint32_t off = sw128(row * 128 + kk * 32 + ((lane >> 3) & 1) * 16);
            ldsm_x4(bh[bi], base + R_B + off);
        }
        #pragma unroll
        for (int mi = 0; mi < 4; mi++)
            #pragma unroll
            for (int ni = 0; ni < 4; ni++)
                mma_fp8(acc[mi][ni], ah[mi], &bh[ni >> 1][(ni & 1) * 2]);
    }
}

// ---------------- main GEMM + fused top-2 epilogue ----------------
__global__ __launch_bounds__(256, 2)
void gemm_fp8_top2(const float* __restrict__ br, const float* __restrict__ gum) {
    extern __shared__ char smem[];
    const uint32_t sb = smem_u32(smem);
    const int tid  = threadIdx.x;
    const int lane = tid & 31;
    const int wid  = tid >> 5;
    const int wm   = wid & 1;           // 2 warps over m
    const int wn   = wid >> 1;          // 4 warps over n
    const int m0   = blockIdx.x * BM;   // x fastest: 8 m-CTAs share B tile in L2
    const int nt   = blockIdx.y;
    const int n0   = nt * BN;

    float acc[4][4][4];
    #pragma unroll
    for (int mi = 0; mi < 4; mi++)
        #pragma unroll
        for (int ni = 0; ni < 4; ni++)
            #pragma unroll
            for (int j = 0; j < 4; j++) acc[mi][ni][j] = 0.f;

    // prologue: stages 0..NSTG-2
    #pragma unroll
    for (int s = 0; s < NSTG - 1; s++) {
        load_stage(sb, s, m0, n0, s * BK, tid);
        cp_commit();
    }
    // single-barrier pipeline: [wait][sync][load pf][commit][compute k]
    for (int k = 0; k < NKT; k++) {
        cp_wait<NSTG - 2>();
        __syncthreads();
        int pf = k + NSTG - 1;
        if (pf < NKT) load_stage(sb, pf % NSTG, m0, n0, pf * BK, tid);
        cp_commit();
        compute_stage(sb, k % NSTG, lane, wm, wn, acc);
    }
    __syncthreads();   // before smem reuse in epilogue

    // ---- epilogue: acc/16 + br + gumbel, per-row top-2 ----
    const int g = lane >> 2, t = lane & 3;
    float* pv = (float*)smem;                   // [128][4][2]
    int*   pidx = (int*)(smem + 8192);

    float2 brv[4];
    bool valid[4];
    #pragma unroll
    for (int ni = 0; ni < 4; ni++) {
        int col = wn * 32 + ni * 8 + 2 * t;
        valid[ni] = (n0 + col) < VOC;           // pairs all-or-none (VOC even)
        brv[ni] = valid[ni] ? *(const float2*)(br + n0 + col) : make_float2(0.f, 0.f);
    }

    #pragma unroll
    for (int mi = 0; mi < 4; mi++) {
        #pragma unroll
        for (int h = 0; h < 2; h++) {
            int rl = wm * 64 + mi * 16 + g + h * 8;
            const float* gr = gum + (size_t)(m0 + rl) * VOC + n0;
            float m1 = -FLT_MAX, m2 = -FLT_MAX;
            int   i1 = 0x7fffffff, i2 = 0x7fffffff;
            #pragma unroll
            for (int ni = 0; ni < 4; ni++) {
                if (valid[ni]) {
                    int col = wn * 32 + ni * 8 + 2 * t;
                    float2 gg = *(const float2*)(gr + col);
                    float v0 = fmaf(acc[mi][ni][h * 2 + 0], INVSC, brv[ni].x + gg.x);
                    float v1 = fmaf(acc[mi][ni][h * 2 + 1], INVSC, brv[ni].y + gg.y);
                    top2_merge(v0, n0 + col,     m1, i1, m2, i2);
                    top2_merge(v1, n0 + col + 1, m1, i1, m2, i2);
                }
            }
            #pragma unroll
            for (int s = 1; s < 4; s <<= 1) {
                float o1 = __shfl_xor_sync(0xffffffffu, m1, s);
                int   oi1 = __shfl_xor_sync(0xffffffffu, i1, s);
                float o2 = __shfl_xor_sync(0xffffffffu, m2, s);
                int   oi2 = __shfl_xor_sync(0xffffffffu, i2, s);
                top2_merge(o1, oi1, m1, i1, m2, i2);
                top2_merge(o2, oi2, m1, i1, m2, i2);
            }
            if (t == 0) {
                pv[(rl * 4 + wn) * 2 + 0] = m1;
                pv[(rl * 4 + wn) * 2 + 1] = m2;
                pidx[(rl * 4 + wn) * 2 + 0] = i1;
                pidx[(rl * 4 + wn) * 2 + 1] = i2;
            }
        }
    }
    __syncthreads();
    if (tid < BM) {
        float m1 = -FLT_MAX, m2 = -FLT_MAX;
        int   i1 = 0x7fffffff, i2 = 0x7fffffff;
        #pragma unroll
        for (int w = 0; w < 4; w++) {
            top2_merge(pv[(tid * 4 + w) * 2 + 0], pidx[(tid * 4 + w) * 2 + 0], m1, i1, m2, i2);
            top2_merge(pv[(tid * 4 + w) * 2 + 1], pidx[(tid * 4 + w) * 2 + 1], m1, i1, m2, i2);
        }
        size_t o = (size_t)(m0 + tid) * NT2 + nt;
        g_p1v[o] = m1; g_p1i[o] = i1;
        g_p2v[o] = m2; g_p2i[o] = i2;
    }
}

// ---------------- rescue + per-token contrib: 1 warp per token ----------------
__global__ __launch_bounds__(256)
void rescue_contrib(const float* __restrict__ A,    // fp32 [1024,768]
                    const float* __restrict__ Wr,   // fp32 [21128,768]
                    const float* __restrict__ br,
                    const float* __restrict__ gum,
                    const float* __restrict__ sim,
                    const int* __restrict__ ids,
                    const void* __restrict__ mask) {
    __shared__ int s_cand[8][128];
    __shared__ int s_cnt[8];
    const int w    = threadIdx.x >> 5;
    const int lane = threadIdx.x & 31;
    const int tok  = blockIdx.x * 8 + w;   // 128 blocks * 8 warps = 1024 tokens

    // 1) global fp8 argmax over tile top-1s
    float M = -FLT_MAX;
    int Mi = 0x7fffffff;
    const size_t base = (size_t)tok * NT2;
    for (int n = lane; n < NT2; n += 32) {
        float v = g_p1v[base + n];
        int   i = g_p1i[base + n];
        if (v > M || (v == M && i < Mi)) { M = v; Mi = i; }
    }
    #pragma unroll
    for (int s = 16; s > 0; s >>= 1) {
        float ov = __shfl_xor_sync(0xffffffffu, M, s);
        int   oi = __shfl_xor_sync(0xffffffffu, Mi, s);
        if (ov > M || (ov == M && oi < Mi)) { M = ov; Mi = oi; }
    }

    // 2) candidates within THETA of M
    if (lane == 0) s_cnt[w] = 0;
    __syncwarp();
    const float thr = M - THETA;
    for (int n = lane; n < NT2; n += 32) {
        float v1 = g_p1v[base + n]; int i1 = g_p1i[base + n];
        float v2 = g_p2v[base + n]; int i2 = g_p2i[base + n];
        if (v1 > thr && i1 != Mi) {
            int p = atomicAdd(&s_cnt[w], 1);
            if (p < 127) s_cand[w][p] = i1;
        }
        if (v2 > thr && i2 != Mi && i2 != 0x7fffffff) {
            int p = atomicAdd(&s_cnt[w], 1);
            if (p < 127) s_cand[w][p] = i2;
        }
    }
    __syncwarp();
    int ncand = min(s_cnt[w], 127);

    int besti = Mi;
    if (ncand > 0) {
        // exact fp32 rescore of incumbent + candidates
        float ar[24];
        #pragma unroll
        for (int j = 0; j < 24; j++)
            ar[j] = A[(size_t)tok * KDIM + j * 32 + lane];

        float bestv = -FLT_MAX;
        besti = 0x7fffffff;
        for (int cix = -1; cix < ncand; cix++) {
            int c = (cix < 0) ? Mi : s_cand[w][cix];
            const float* wrow = Wr + (size_t)c * KDIM;
            float s = 0.f;
            #pragma unroll
            for (int j = 0; j < 24; j++)
                s = fmaf(ar[j], wrow[j * 32 + lane], s);
            #pragma unroll
            for (int sh = 16; sh > 0; sh >>= 1)
                s += __shfl_xor_sync(0xffffffffu, s, sh);
            if (lane == 0) {
                float sc = s + br[c] + gum[(size_t)tok * VOC + c];
                if (sc > bestv || (sc == bestv && c < besti)) { bestv = sc; besti = c; }
            }
        }
        besti = __shfl_sync(0xffffffffu, besti, 0);
    }

    // 3) contrib
    if (lane == 0) {
        const int id = ids[tok];
        const int kind = g_mask_kind;
        bool ch;
        if (kind == 1)      ch = ((const int*)mask)[id] != 0;
        else if (kind == 2) ch = ((const float*)mask)[id] != 0.0f;
        else                ch = ((const unsigned char*)mask)[id] != 0;
        g_contrib[tok] = ch ? (1.0f - sim[(size_t)id * VOC + besti]) : 0.0f;
    }
}

// ---------------- final deterministic sum ----------------
__global__ void final_sum(float* __restrict__ out, int out_size) {
    __shared__ float red[1024];
    const int t = threadIdx.x;
    red[t] = g_contrib[t];
    __syncthreads();
    for (int s = 512; s > 0; s >>= 1) {
        if (t < s) red[t] += red[t + s];
        __syncthreads();
    }
    if (t == 0) {
        float L = red[0] * (1.0f / 1024.0f);
        for (int k = 0; k < out_size; k++) out[k] = L;
    }
}

extern "C" void kernel_launch(void* const* d_in, const int* in_sizes, int n_in,
                              void* d_out, int out_size) {
    const float* seq  = (const float*)d_in[0];   // [8,128,768]
    const float* Wr   = (const float*)d_in[1];   // [21128,768]
    const float* br   = (const float*)d_in[2];   // [21128]
    const float* sim  = (const float*)d_in[3];   // [21128,21128]
    const float* gum  = (const float*)d_in[4];   // [8,128,21128]
    const int*   ids  = (const int*)d_in[5];     // [8,128]
    const void*  mask = d_in[6];                 // [21128] bool-ish

    static bool attr_set = false;
    if (!attr_set) {
        cudaFuncSetAttribute(gemm_fp8_top2,
                             cudaFuncAttributeMaxDynamicSharedMemorySize, SM_TOTAL_G);
        attr_set = true;
    }

    convert_fp8<<<2048, 256>>>(seq, Wr, (const unsigned char*)mask);

    dim3 grid(M_TOK / BM, NT2);   // (8, 166); x fastest -> B tile shared in L2
    gemm_fp8_top2<<<grid, 256, SM_TOTAL_G>>>(br, gum);

    rescue_contrib<<<128, 256>>>(seq, Wr, br, gum, sim, ids, mask);
    final_sum<<<1, 1024>>>((float*)d_out, out_size);
}

// round 14
// speedup vs baseline: 1.0060x; 1.0060x over previous
#include <cuda_runtime.h>
#include <cuda_bf16.h>
#include <cfloat>
#include <cstdint>

// ---------------- problem constants ----------------
#define M_TOK   1024
#define KDIM    768
#define VOC     21128
#define VP      21248          // padded vocab: 166 * 128
#define NT2     166            // n-tiles of 128
#define BM      128
#define BN      128
#define BK      128            // fp8 elems per k-chunk = 128 bytes/row
#define NKT     6              // 768/128
#define NSTG    3
#define THETA   0.25f          // rescue threshold (~16 sigma of fp8 dot error)
#define WSCALE  16.0f          // W pre-scale before fp8 quant
#define INVSC   0.0625f        // 1/16 applied to acc in epilogue

// smem per stage: A 16K | B 16K
#define STG_BYTES 32768
#define R_B       16384
#define SM_TOTAL_G (NSTG * STG_BYTES)   // 98304 (epilogue reuses stage 0)

// ---------------- device scratch (allocation-free) ----------------
__device__ uint8_t g_Wq[(size_t)VP * KDIM];
__device__ uint8_t g_Aq[(size_t)M_TOK * KDIM];
__device__ float g_p1v[(size_t)M_TOK * NT2];
__device__ int   g_p1i[(size_t)M_TOK * NT2];
__device__ float g_p2v[(size_t)M_TOK * NT2];
__device__ int   g_p2i[(size_t)M_TOK * NT2];
__device__ float g_contrib[M_TOK];
__device__ int   g_mask_kind;

// ---------------- PTX helpers (portable, no 'a'-feature) ----------------
__device__ __forceinline__ uint32_t smem_u32(const void* p) {
    uint32_t a;
    asm("{ .reg .u64 t; cvta.to.shared.u64 t, %1; cvt.u32.u64 %0, t; }" : "=r"(a) : "l"(p));
    return a;
}
__device__ __forceinline__ void cp16(uint32_t dst, const void* src) {
    asm volatile("cp.async.cg.shared.global [%0], [%1], 16;" :: "r"(dst), "l"(src));
}
__device__ __forceinline__ void cp_commit() {
    asm volatile("cp.async.commit_group;" ::: "memory");
}
template <int N>
__device__ __forceinline__ void cp_wait() {
    asm volatile("cp.async.wait_group %0;" :: "n"(N) : "memory");
}
__device__ __forceinline__ void ldsm_x4(uint32_t* r, uint32_t addr) {
    asm volatile("ldmatrix.sync.aligned.m8n8.x4.shared.b16 {%0,%1,%2,%3}, [%4];"
                 : "=r"(r[0]), "=r"(r[1]), "=r"(r[2]), "=r"(r[3]) : "r"(addr));
}
// fp8 e4m3 MMA: m16n8k32, same fragment register counts as bf16 m16n8k16
__device__ __forceinline__ void mma_fp8(float* c, const uint32_t* a, const uint32_t* b) {
    asm volatile(
        "mma.sync.aligned.m16n8k32.row.col.f32.e4m3.e4m3.f32 "
        "{%0,%1,%2,%3}, {%4,%5,%6,%7}, {%8,%9}, {%0,%1,%2,%3};"
        : "+f"(c[0]), "+f"(c[1]), "+f"(c[2]), "+f"(c[3])
        : "r"(a[0]), "r"(a[1]), "r"(a[2]), "r"(a[3]), "r"(b[0]), "r"(b[1]));
}
__device__ __forceinline__ uint32_t sw128(uint32_t b) { return b ^ ((b >> 3) & 0x70); }

// pack 4 consecutive floats -> 4 e4m3 bytes (byte0 = x0). PTX cvt: first src -> upper half.
__device__ __forceinline__ uint32_t pack_e4m3_4(float x0, float x1, float x2, float x3) {
    uint16_t lo, hi;
    asm("cvt.rn.satfinite.e4m3x2.f32 %0, %1, %2;" : "=h"(lo) : "f"(x1), "f"(x0));
    asm("cvt.rn.satfinite.e4m3x2.f32 %0, %1, %2;" : "=h"(hi) : "f"(x3), "f"(x2));
    return (uint32_t)lo | ((uint32_t)hi << 16);
}

// top-2 merge keeping first-occurrence (min idx) semantics
__device__ __forceinline__ void top2_merge(float v, int i, float& m1, int& i1,
                                           float& m2, int& i2) {
    if (v > m1 || (v == m1 && i < i1)) {
        m2 = m1; i2 = i1; m1 = v; i1 = i;
    } else if (v > m2 || (v == m2 && i < i2)) {
        m2 = v; i2 = i;
    }
}

// ---------------- convert f32 -> fp8 (W scaled by 16) + fused mask probe ----------------
__global__ void convert_fp8(const float* __restrict__ A, const float* __restrict__ W,
                            const unsigned char* __restrict__ mb) {
    // block 0 also runs the mask-dtype probe
    if (blockIdx.x == 0) {
        __shared__ int nz[4];
        if (threadIdx.x < 4) nz[threadIdx.x] = 0;
        __syncthreads();
        int c[4] = {0, 0, 0, 0};
        for (int i = threadIdx.x; i < VOC; i += blockDim.x)
            if (mb[i]) c[i & 3]++;
        #pragma unroll
        for (int r = 0; r < 4; r++)
            if (c[r]) atomicAdd(&nz[r], c[r]);
        __syncthreads();
        if (threadIdx.x == 0) {
            int kind = 0;
            if (nz[0] > 0 && nz[1] == 0 && nz[2] == 0 && nz[3] == 0) kind = 1;
            else if (nz[0] == 0 && (nz[2] > 0 || nz[3] > 0))          kind = 2;
            g_mask_kind = kind;
        }
    }
    const size_t nW8 = (size_t)VP * KDIM / 8;
    const size_t nA8 = (size_t)M_TOK * KDIM / 8;
    const size_t nV8 = (size_t)VOC * KDIM / 8;
    for (size_t i = (size_t)blockIdx.x * blockDim.x + threadIdx.x;
         i < nW8 + nA8; i += (size_t)gridDim.x * blockDim.x) {
        uint2 out;
        if (i < nW8) {
            size_t e = i * 8;
            if (i < nV8) {
                float4 v0 = *(const float4*)(W + e);
                float4 v1 = *(const float4*)(W + e + 4);
                out.x = pack_e4m3_4(v0.x * WSCALE, v0.y * WSCALE, v0.z * WSCALE, v0.w * WSCALE);
                out.y = pack_e4m3_4(v1.x * WSCALE, v1.y * WSCALE, v1.z * WSCALE, v1.w * WSCALE);
            } else {
                out.x = 0u; out.y = 0u;
            }
            *(uint2*)(g_Wq + e) = out;
        } else {
            size_t e = (i - nW8) * 8;
            float4 v0 = *(const float4*)(A + e);
            float4 v1 = *(const float4*)(A + e + 4);
            out.x = pack_e4m3_4(v0.x, v0.y, v0.z, v0.w);
            out.y = pack_e4m3_4(v1.x, v1.y, v1.z, v1.w);
            *(uint2*)(g_Aq + e) = out;
        }
    }
}

// ---------------- stage loader: 128x128B A + 128x128B B (fp8) ----------------
__device__ __forceinline__ void load_stage(uint32_t sb, int buf, int m0, int n0,
                                           int kt, int tid) {
    uint32_t base = sb + buf * STG_BYTES;
    #pragma unroll
    for (int i = 0; i < 4; i++) {
        int id = tid + i * 256;                  // 0..1023
        int row = id >> 3, c = id & 7;           // 128 rows x 8 x 16B
        uint32_t so = sw128(row * 128 + c * 16);
        cp16(base + so,       g_Aq + (size_t)(m0 + row) * KDIM + kt + c * 16);
        cp16(base + R_B + so, g_Wq + (size_t)(n0 + row) * KDIM + kt + c * 16);
    }
}

// ---------------- stage compute: 4 x k32, 64 fp8-MMA per warp ----------------
__device__ __forceinline__ void compute_stage(uint32_t sb, int buf, int lane,
                                              int wm, int wn, float acc[4][4][4]) {
    uint32_t base = sb + buf * STG_BYTES;
    #pragma unroll
    for (int kk = 0; kk < 4; kk++) {
        uint32_t ah[4][4], bh[2][4];
        #pragma unroll
        for (int mi = 0; mi < 4; mi++) {
            int row = wm * 64 + mi * 16 + (lane & 15);
            uint32_t off = sw128(row * 128 + kk * 32 + ((lane >> 4) & 1) * 16);
            ldsm_x4(ah[mi], base + off);
        }
        #pragma unroll
        for (int bi = 0; bi < 2; bi++) {
            int row = wn * 32 + bi * 16 + (lane & 7) + ((lane >> 4) & 1) * 8;
            uint32_t off = sw128(row * 128 + kk * 32 + ((lane >> 3) & 1) * 16);
            ldsm_x4(bh[bi], base + R_B + off);
        }
        #pragma unroll
        for (int mi = 0; mi < 4; mi++)
            #pragma unroll
            for (int ni = 0; ni < 4; ni++)
                mma_fp8(acc[mi][ni], ah[mi], &bh[ni >> 1][(ni & 1) * 2]);
    }
}

// ---------------- main GEMM + fused top-2 epilogue ----------------
__global__ __launch_bounds__(256, 2)
void gemm_fp8_top2(const float* __restrict__ br, const float* __restrict__ gum) {
    extern __shared__ char smem[];
    const uint32_t sb = smem_u32(smem);
    const int tid  = threadIdx.x;
    const int lane = tid & 31;
    const int wid  = tid >> 5;
    const int wm   = wid & 1;           // 2 warps over m
    const int wn   = wid >> 1;          // 4 warps over n
    const int m0   = blockIdx.x * BM;   // x fastest: 8 m-CTAs share B tile in L2
    const int nt   = blockIdx.y;
    const int n0   = nt * BN;

    float acc[4][4][4];
    #pragma unroll
    for (int mi = 0; mi < 4; mi++)
        #pragma unroll
        for (int ni = 0; ni < 4; ni++)
            #pragma unroll
            for (int j = 0; j < 4; j++) acc[mi][ni][j] = 0.f;

    // prologue: stages 0..NSTG-2
    #pragma unroll
    for (int s = 0; s < NSTG - 1; s++) {
        load_stage(sb, s, m0, n0, s * BK, tid);
        cp_commit();
    }
    // single-barrier pipeline: [wait][sync][load pf][commit][compute k]
    for (int k = 0; k < NKT; k++) {
        cp_wait<NSTG - 2>();
        __syncthreads();
        int pf = k + NSTG - 1;
        if (pf < NKT) load_stage(sb, pf % NSTG, m0, n0, pf * BK, tid);
        cp_commit();
        compute_stage(sb, k % NSTG, lane, wm, wn, acc);
    }
    __syncthreads();   // before smem reuse in epilogue

    // ---- epilogue: acc/16 + br + gumbel, per-row top-2 ----
    const int g = lane >> 2, t = lane & 3;
    float* pv = (float*)smem;                   // [128][4][2]
    int*   pidx = (int*)(smem + 8192);

    float2 brv[4];
    bool valid[4];
    #pragma unroll
    for (int ni = 0; ni < 4; ni++) {
        int col = wn * 32 + ni * 8 + 2 * t;
        valid[ni] = (n0 + col) < VOC;           // pairs all-or-none (VOC even)
        brv[ni] = valid[ni] ? *(const float2*)(br + n0 + col) : make_float2(0.f, 0.f);
    }

    #pragma unroll
    for (int mi = 0; mi < 4; mi++) {
        #pragma unroll
        for (int h = 0; h < 2; h++) {
            int rl = wm * 64 + mi * 16 + g + h * 8;
            const float* gr = gum + (size_t)(m0 + rl) * VOC + n0;
            float m1 = -FLT_MAX, m2 = -FLT_MAX;
            int   i1 = 0x7fffffff, i2 = 0x7fffffff;
            #pragma unroll
            for (int ni = 0; ni < 4; ni++) {
                if (valid[ni]) {
                    int col = wn * 32 + ni * 8 + 2 * t;
                    float2 gg = *(const float2*)(gr + col);
                    float v0 = fmaf(acc[mi][ni][h * 2 + 0], INVSC, brv[ni].x + gg.x);
                    float v1 = fmaf(acc[mi][ni][h * 2 + 1], INVSC, brv[ni].y + gg.y);
                    top2_merge(v0, n0 + col,     m1, i1, m2, i2);
                    top2_merge(v1, n0 + col + 1, m1, i1, m2, i2);
                }
            }
            #pragma unroll
            for (int s = 1; s < 4; s <<= 1) {
                float o1 = __shfl_xor_sync(0xffffffffu, m1, s);
                int   oi1 = __shfl_xor_sync(0xffffffffu, i1, s);
                float o2 = __shfl_xor_sync(0xffffffffu, m2, s);
                int   oi2 = __shfl_xor_sync(0xffffffffu, i2, s);
                top2_merge(o1, oi1, m1, i1, m2, i2);
                top2_merge(o2, oi2, m1, i1, m2, i2);
            }
            if (t == 0) {
                pv[(rl * 4 + wn) * 2 + 0] = m1;
                pv[(rl * 4 + wn) * 2 + 1] = m2;
                pidx[(rl * 4 + wn) * 2 + 0] = i1;
                pidx[(rl * 4 + wn) * 2 + 1] = i2;
            }
        }
    }
    __syncthreads();
    if (tid < BM) {
        float m1 = -FLT_MAX, m2 = -FLT_MAX;
        int   i1 = 0x7fffffff, i2 = 0x7fffffff;
        #pragma unroll
        for (int w = 0; w < 4; w++) {
            top2_merge(pv[(tid * 4 + w) * 2 + 0], pidx[(tid * 4 + w) * 2 + 0], m1, i1, m2, i2);
            top2_merge(pv[(tid * 4 + w) * 2 + 1], pidx[(tid * 4 + w) * 2 + 1], m1, i1, m2, i2);
        }
        size_t o = (size_t)(m0 + tid) * NT2 + nt;
        g_p1v[o] = m1; g_p1i[o] = i1;
        g_p2v[o] = m2; g_p2i[o] = i2;
    }
}

// ---------------- rescue + per-token contrib: 1 warp per token ----------------
__global__ __launch_bounds__(256)
void rescue_contrib(const float* __restrict__ A,    // fp32 [1024,768]
                    const float* __restrict__ Wr,   // fp32 [21128,768]
                    const float* __restrict__ br,
                    const float* __restrict__ gum,
                    const float* __restrict__ sim,
                    const int* __restrict__ ids,
                    const void* __restrict__ mask) {
    __shared__ int s_cand[8][128];
    __shared__ int s_cnt[8];
    const int w    = threadIdx.x >> 5;
    const int lane = threadIdx.x & 31;
    const int tok  = blockIdx.x * 8 + w;   // 128 blocks * 8 warps = 1024 tokens

    // 1) global fp8 argmax over tile top-1s
    float M = -FLT_MAX;
    int Mi = 0x7fffffff;
    const size_t base = (size_t)tok * NT2;
    for (int n = lane; n < NT2; n += 32) {
        float v = g_p1v[base + n];
        int   i = g_p1i[base + n];
        if (v > M || (v == M && i < Mi)) { M = v; Mi = i; }
    }
    #pragma unroll
    for (int s = 16; s > 0; s >>= 1) {
        float ov = __shfl_xor_sync(0xffffffffu, M, s);
        int   oi = __shfl_xor_sync(0xffffffffu, Mi, s);
        if (ov > M || (ov == M && oi < Mi)) { M = ov; Mi = oi; }
    }

    // 2) candidates within THETA of M
    if (lane == 0) s_cnt[w] = 0;
    __syncwarp();
    const float thr = M - THETA;
    for (int n = lane; n < NT2; n += 32) {
        float v1 = g_p1v[base + n]; int i1 = g_p1i[base + n];
        float v2 = g_p2v[base + n]; int i2 = g_p2i[base + n];
        if (v1 > thr && i1 != Mi) {
            int p = atomicAdd(&s_cnt[w], 1);
            if (p < 127) s_cand[w][p] = i1;
        }
        if (v2 > thr && i2 != Mi && i2 != 0x7fffffff) {
            int p = atomicAdd(&s_cnt[w], 1);
            if (p < 127) s_cand[w][p] = i2;
        }
    }
    __syncwarp();
    int ncand = min(s_cnt[w], 127);

    int besti = Mi;
    if (ncand > 0) {
        // exact fp32 rescore of incumbent + candidates
        float ar[24];
        #pragma unroll
        for (int j = 0; j < 24; j++)
            ar[j] = A[(size_t)tok * KDIM + j * 32 + lane];

        float bestv = -FLT_MAX;
        besti = 0x7fffffff;
        for (int cix = -1; cix < ncand; cix++) {
            int c = (cix < 0) ? Mi : s_cand[w][cix];
            const float* wrow = Wr + (size_t)c * KDIM;
            float s = 0.f;
            #pragma unroll
            for (int j = 0; j < 24; j++)
                s = fmaf(ar[j], wrow[j * 32 + lane], s);
            #pragma unroll
            for (int sh = 16; sh > 0; sh >>= 1)
                s += __shfl_xor_sync(0xffffffffu, s, sh);
            if (lane == 0) {
                float sc = s + br[c] + gum[(size_t)tok * VOC + c];
                if (sc > bestv || (sc == bestv && c < besti)) { bestv = sc; besti = c; }
            }
        }
        besti = __shfl_sync(0xffffffffu, besti, 0);
    }

    // 3) contrib
    if (lane == 0) {
        const int id = ids[tok];
        const int kind = g_mask_kind;
        bool ch;
        if (kind == 1)      ch = ((const int*)mask)[id] != 0;
        else if (kind == 2) ch = ((const float*)mask)[id] != 0.0f;
        else                ch = ((const unsigned char*)mask)[id] != 0;
        g_contrib[tok] = ch ? (1.0f - sim[(size_t)id * VOC + besti]) : 0.0f;
    }
}

// ---------------- final deterministic sum ----------------
__global__ void final_sum(float* __restrict__ out, int out_size) {
    __shared__ float red[1024];
    const int t = threadIdx.x;
    red[t] = g_contrib[t];
    __syncthreads();
    for (int s = 512; s > 0; s >>= 1) {
        if (t < s) red[t] += red[t + s];
        __syncthreads();
    }
    if (t == 0) {
        float L = red[0] * (1.0f / 1024.0f);
        for (int k = 0; k < out_size; k++) out[k] = L;
    }
}

extern "C" void kernel_launch(void* const* d_in, const int* in_sizes, int n_in,
                              void* d_out, int out_size) {
    const float* seq  = (const float*)d_in[0];   // [8,128,768]
    const float* Wr   = (const float*)d_in[1];   // [21128,768]
    const float* br   = (const float*)d_in[2];   // [21128]
    const float* sim  = (const float*)d_in[3];   // [21128,21128]
    const float* gum  = (const float*)d_in[4];   // [8,128,21128]
    const int*   ids  = (const int*)d_in[5];     // [8,128]
    const void*  mask = d_in[6];                 // [21128] bool-ish

    static bool attr_set = false;
    if (!attr_set) {
        cudaFuncSetAttribute(gemm_fp8_top2,
                             cudaFuncAttributeMaxDynamicSharedMemorySize, SM_TOTAL_G);
        attr_set = true;
    }

    convert_fp8<<<2048, 256>>>(seq, Wr, (const unsigned char*)mask);

    dim3 grid(M_TOK / BM, NT2);   // (8, 166); x fastest -> B tile shared in L2
    gemm_fp8_top2<<<grid, 256, SM_TOTAL_G>>>(br, gum);

    rescue_contrib<<<128, 256>>>(seq, Wr, br, gum, sim, ids, mask);
    final_sum<<<1, 1024>>>((float*)d_out, out_size);
}

// round 15
// speedup vs baseline: 1.0163x; 1.0103x over previous
#include <cuda_runtime.h>
#include <cuda_bf16.h>
#include <cfloat>
#include <cstdint>

// ---------------- problem constants ----------------
#define M_TOK   1024
#define KDIM    768
#define VOC     21128
#define VP      21248          // padded vocab: 166 * 128
#define NT2     166            // n-tiles of 128
#define BM      128
#define BN      128
#define BK      128            // fp8 elems per k-chunk = 128 bytes/row
#define NKT     6              // 768/128
#define NSTG    3
#define THETA   0.25f          // rescue threshold (~16 sigma of fp8 dot error)
#define WSCALE  16.0f          // W pre-scale before fp8 quant
#define INVSC   0.0625f        // 1/16 applied to acc in epilogue

// smem per stage: A 16K | B 16K
#define STG_BYTES 32768
#define R_B       16384
#define SM_TOTAL_G (NSTG * STG_BYTES)   // 98304 (epilogue reuses stage 0)

// ---------------- device scratch (allocation-free) ----------------
__device__ uint8_t g_Wq[(size_t)VP * KDIM];
__device__ uint8_t g_Aq[(size_t)M_TOK * KDIM];
__device__ float g_p1v[(size_t)M_TOK * NT2];
__device__ int   g_p1i[(size_t)M_TOK * NT2];
__device__ float g_p2v[(size_t)M_TOK * NT2];
__device__ int   g_p2i[(size_t)M_TOK * NT2];
__device__ float g_contrib[M_TOK];
__device__ int   g_mask_kind;

// ---------------- PTX helpers (portable, no 'a'-feature) ----------------
__device__ __forceinline__ uint32_t smem_u32(const void* p) {
    uint32_t a;
    asm("{ .reg .u64 t; cvta.to.shared.u64 t, %1; cvt.u32.u64 %0, t; }" : "=r"(a) : "l"(p));
    return a;
}
__device__ __forceinline__ void cp16(uint32_t dst, const void* src) {
    asm volatile("cp.async.cg.shared.global [%0], [%1], 16;" :: "r"(dst), "l"(src));
}
__device__ __forceinline__ void cp_commit() {
    asm volatile("cp.async.commit_group;" ::: "memory");
}
template <int N>
__device__ __forceinline__ void cp_wait() {
    asm volatile("cp.async.wait_group %0;" :: "n"(N) : "memory");
}
__device__ __forceinline__ void ldsm_x4(uint32_t* r, uint32_t addr) {
    asm volatile("ldmatrix.sync.aligned.m8n8.x4.shared.b16 {%0,%1,%2,%3}, [%4];"
                 : "=r"(r[0]), "=r"(r[1]), "=r"(r[2]), "=r"(r[3]) : "r"(addr));
}
// fp8 e4m3 MMA: m16n8k32, same fragment register counts as bf16 m16n8k16
__device__ __forceinline__ void mma_fp8(float* c, const uint32_t* a, const uint32_t* b) {
    asm volatile(
        "mma.sync.aligned.m16n8k32.row.col.f32.e4m3.e4m3.f32 "
        "{%0,%1,%2,%3}, {%4,%5,%6,%7}, {%8,%9}, {%0,%1,%2,%3};"
        : "+f"(c[0]), "+f"(c[1]), "+f"(c[2]), "+f"(c[3])
        : "r"(a[0]), "r"(a[1]), "r"(a[2]), "r"(a[3]), "r"(b[0]), "r"(b[1]));
}
__device__ __forceinline__ uint32_t sw128(uint32_t b) { return b ^ ((b >> 3) & 0x70); }

// pack 4 consecutive floats -> 4 e4m3 bytes (byte0 = x0). PTX cvt: first src -> upper half.
__device__ __forceinline__ uint32_t pack_e4m3_4(float x0, float x1, float x2, float x3) {
    uint16_t lo, hi;
    asm("cvt.rn.satfinite.e4m3x2.f32 %0, %1, %2;" : "=h"(lo) : "f"(x1), "f"(x0));
    asm("cvt.rn.satfinite.e4m3x2.f32 %0, %1, %2;" : "=h"(hi) : "f"(x3), "f"(x2));
    return (uint32_t)lo | ((uint32_t)hi << 16);
}

// top-2 merge keeping first-occurrence (min idx) semantics
__device__ __forceinline__ void top2_merge(float v, int i, float& m1, int& i1,
                                           float& m2, int& i2) {
    if (v > m1 || (v == m1 && i < i1)) {
        m2 = m1; i2 = i1; m1 = v; i1 = i;
    } else if (v > m2 || (v == m2 && i < i2)) {
        m2 = v; i2 = i;
    }
}

// ---------------- convert f32 -> fp8 (W scaled by 16) + fused mask probe ----------------
__global__ void convert_fp8(const float* __restrict__ A, const float* __restrict__ W,
                            const unsigned char* __restrict__ mb) {
    // block 0 also runs the mask-dtype probe
    if (blockIdx.x == 0) {
        __shared__ int nz[4];
        if (threadIdx.x < 4) nz[threadIdx.x] = 0;
        __syncthreads();
        int c[4] = {0, 0, 0, 0};
        for (int i = threadIdx.x; i < VOC; i += blockDim.x)
            if (mb[i]) c[i & 3]++;
        #pragma unroll
        for (int r = 0; r < 4; r++)
            if (c[r]) atomicAdd(&nz[r], c[r]);
        __syncthreads();
        if (threadIdx.x == 0) {
            int kind = 0;
            if (nz[0] > 0 && nz[1] == 0 && nz[2] == 0 && nz[3] == 0) kind = 1;
            else if (nz[0] == 0 && (nz[2] > 0 || nz[3] > 0))          kind = 2;
            g_mask_kind = kind;
        }
    }
    const size_t nW8 = (size_t)VP * KDIM / 8;
    const size_t nA8 = (size_t)M_TOK * KDIM / 8;
    const size_t nV8 = (size_t)VOC * KDIM / 8;
    for (size_t i = (size_t)blockIdx.x * blockDim.x + threadIdx.x;
         i < nW8 + nA8; i += (size_t)gridDim.x * blockDim.x) {
        uint2 out;
        if (i < nW8) {
            size_t e = i * 8;
            if (i < nV8) {
                float4 v0 = *(const float4*)(W + e);
                float4 v1 = *(const float4*)(W + e + 4);
                out.x = pack_e4m3_4(v0.x * WSCALE, v0.y * WSCALE, v0.z * WSCALE, v0.w * WSCALE);
                out.y = pack_e4m3_4(v1.x * WSCALE, v1.y * WSCALE, v1.z * WSCALE, v1.w * WSCALE);
            } else {
                out.x = 0u; out.y = 0u;
            }
            *(uint2*)(g_Wq + e) = out;
        } else {
            size_t e = (i - nW8) * 8;
            float4 v0 = *(const float4*)(A + e);
            float4 v1 = *(const float4*)(A + e + 4);
            out.x = pack_e4m3_4(v0.x, v0.y, v0.z, v0.w);
            out.y = pack_e4m3_4(v1.x, v1.y, v1.z, v1.w);
            *(uint2*)(g_Aq + e) = out;
        }
    }
}

// ---------------- stage loader: 128x128B A + 128x128B B (fp8) ----------------
__device__ __forceinline__ void load_stage(uint32_t sb, int buf, int m0, int n0,
                                           int kt, int tid) {
    uint32_t base = sb + buf * STG_BYTES;
    #pragma unroll
    for (int i = 0; i < 4; i++) {
        int id = tid + i * 256;                  // 0..1023
        int row = id >> 3, c = id & 7;           // 128 rows x 8 x 16B
        uint32_t so = sw128(row * 128 + c * 16);
        cp16(base + so,       g_Aq + (size_t)(m0 + row) * KDIM + kt + c * 16);
        cp16(base + R_B + so, g_Wq + (size_t)(n0 + row) * KDIM + kt + c * 16);
    }
}

// ---------------- stage compute: 4 x k32, 64 fp8-MMA per warp ----------------
__device__ __forceinline__ void compute_stage(uint32_t sb, int buf, int lane,
                                              int wm, int wn, float acc[4][4][4]) {
    uint32_t base = sb + buf * STG_BYTES;
    #pragma unroll
    for (int kk = 0; kk < 4; kk++) {
        uint32_t ah[4][4], bh[2][4];
        #pragma unroll
        for (int mi = 0; mi < 4; mi++) {
            int row = wm * 64 + mi * 16 + (lane & 15);
            uint32_t off = sw128(row * 128 + kk * 32 + ((lane >> 4) & 1) * 16);
            ldsm_x4(ah[mi], base + off);
        }
        #pragma unroll
        for (int bi = 0; bi < 2; bi++) {
            int row = wn * 32 + bi * 16 + (lane & 7) + ((lane >> 4) & 1) * 8;
            uint32_t off = sw128(row * 128 + kk * 32 + ((lane >> 3) & 1) * 16);
            ldsm_x4(bh[bi], base + R_B + off);
        }
        #pragma unroll
        for (int mi = 0; mi < 4; mi++)
            #pragma unroll
            for (int ni = 0; ni < 4; ni++)
                mma_fp8(acc[mi][ni], ah[mi], &bh[ni >> 1][(ni & 1) * 2]);
    }
}

// ---------------- main GEMM + fused top-2 epilogue ----------------
__global__ __launch_bounds__(256, 2)
void gemm_fp8_top2(const float* __restrict__ br, const float* __restrict__ gum) {
    extern __shared__ char smem[];
    const uint32_t sb = smem_u32(smem);
    const int tid  = threadIdx.x;
    const int lane = tid & 31;
    const int wid  = tid >> 5;
    const int wm   = wid & 1;           // 2 warps over m
    const int wn   = wid >> 1;          // 4 warps over n
    const int m0   = blockIdx.x * BM;   // x fastest: 8 m-CTAs share B tile in L2
    const int nt   = blockIdx.y;
    const int n0   = nt * BN;

    float acc[4][4][4];
    #pragma unroll
    for (int mi = 0; mi < 4; mi++)
        #pragma unroll
        for (int ni = 0; ni < 4; ni++)
            #pragma unroll
            for (int j = 0; j < 4; j++) acc[mi][ni][j] = 0.f;

    // prologue: stages 0..NSTG-2
    #pragma unroll
    for (int s = 0; s < NSTG - 1; s++) {
        load_stage(sb, s, m0, n0, s * BK, tid);
        cp_commit();
    }
    // single-barrier pipeline: [wait][sync][load pf][commit][compute k]
    for (int k = 0; k < NKT; k++) {
        cp_wait<NSTG - 2>();
        __syncthreads();
        int pf = k + NSTG - 1;
        if (pf < NKT) load_stage(sb, pf % NSTG, m0, n0, pf * BK, tid);
        cp_commit();
        compute_stage(sb, k % NSTG, lane, wm, wn, acc);
    }
    __syncthreads();   // before smem reuse in epilogue

    // ---- epilogue: acc/16 + br + gumbel, per-row top-2 ----
    const int g = lane >> 2, t = lane & 3;
    float* pv = (float*)smem;                   // [128][4][2]
    int*   pidx = (int*)(smem + 8192);

    float2 brv[4];
    bool valid[4];
    #pragma unroll
    for (int ni = 0; ni < 4; ni++) {
        int col = wn * 32 + ni * 8 + 2 * t;
        valid[ni] = (n0 + col) < VOC;           // pairs all-or-none (VOC even)
        brv[ni] = valid[ni] ? *(const float2*)(br + n0 + col) : make_float2(0.f, 0.f);
    }

    #pragma unroll
    for (int mi = 0; mi < 4; mi++) {
        #pragma unroll
        for (int h = 0; h < 2; h++) {
            int rl = wm * 64 + mi * 16 + g + h * 8;
            const float* gr = gum + (size_t)(m0 + rl) * VOC + n0;
            float m1 = -FLT_MAX, m2 = -FLT_MAX;
            int   i1 = 0x7fffffff, i2 = 0x7fffffff;
            #pragma unroll
            for (int ni = 0; ni < 4; ni++) {
                if (valid[ni]) {
                    int col = wn * 32 + ni * 8 + 2 * t;
                    float2 gg = *(const float2*)(gr + col);
                    float v0 = fmaf(acc[mi][ni][h * 2 + 0], INVSC, brv[ni].x + gg.x);
                    float v1 = fmaf(acc[mi][ni][h * 2 + 1], INVSC, brv[ni].y + gg.y);
                    top2_merge(v0, n0 + col,     m1, i1, m2, i2);
                    top2_merge(v1, n0 + col + 1, m1, i1, m2, i2);
                }
            }
            #pragma unroll
            for (int s = 1; s < 4; s <<= 1) {
                float o1 = __shfl_xor_sync(0xffffffffu, m1, s);
                int   oi1 = __shfl_xor_sync(0xffffffffu, i1, s);
                float o2 = __shfl_xor_sync(0xffffffffu, m2, s);
                int   oi2 = __shfl_xor_sync(0xffffffffu, i2, s);
                top2_merge(o1, oi1, m1, i1, m2, i2);
                top2_merge(o2, oi2, m1, i1, m2, i2);
            }
            if (t == 0) {
                pv[(rl * 4 + wn) * 2 + 0] = m1;
                pv[(rl * 4 + wn) * 2 + 1] = m2;
                pidx[(rl * 4 + wn) * 2 + 0] = i1;
                pidx[(rl * 4 + wn) * 2 + 1] = i2;
            }
        }
    }
    __syncthreads();
    if (tid < BM) {
        float m1 = -FLT_MAX, m2 = -FLT_MAX;
        int   i1 = 0x7fffffff, i2 = 0x7fffffff;
        #pragma unroll
        for (int w = 0; w < 4; w++) {
            top2_merge(pv[(tid * 4 + w) * 2 + 0], pidx[(tid * 4 + w) * 2 + 0], m1, i1, m2, i2);
            top2_merge(pv[(tid * 4 + w) * 2 + 1], pidx[(tid * 4 + w) * 2 + 1], m1, i1, m2, i2);
        }
        size_t o = (size_t)(m0 + tid) * NT2 + nt;
        g_p1v[o] = m1; g_p1i[o] = i1;
        g_p2v[o] = m2; g_p2i[o] = i2;
    }
}

// ---------------- rescue + per-token contrib: 1 warp per token ----------------
__global__ __launch_bounds__(256)
void rescue_contrib(const float* __restrict__ A,    // fp32 [1024,768]
                    const float* __restrict__ Wr,   // fp32 [21128,768]
                    const float* __restrict__ br,
                    const float* __restrict__ gum,
                    const float* __restrict__ sim,
                    const int* __restrict__ ids,
                    const void* __restrict__ mask) {
    __shared__ int s_cand[8][128];
    __shared__ int s_cnt[8];
    const int w    = threadIdx.x >> 5;
    const int lane = threadIdx.x & 31;
    const int tok  = blockIdx.x * 8 + w;   // 128 blocks * 8 warps = 1024 tokens

    // 1) global fp8 argmax over tile top-1s
    float M = -FLT_MAX;
    int Mi = 0x7fffffff;
    const size_t base = (size_t)tok * NT2;
    for (int n = lane; n < NT2; n += 32) {
        float v = g_p1v[base + n];
        int   i = g_p1i[base + n];
        if (v > M || (v == M && i < Mi)) { M = v; Mi = i; }
    }
    #pragma unroll
    for (int s = 16; s > 0; s >>= 1) {
        float ov = __shfl_xor_sync(0xffffffffu, M, s);
        int   oi = __shfl_xor_sync(0xffffffffu, Mi, s);
        if (ov > M || (ov == M && oi < Mi)) { M = ov; Mi = oi; }
    }

    // 2) candidates within THETA of M
    if (lane == 0) s_cnt[w] = 0;
    __syncwarp();
    const float thr = M - THETA;
    for (int n = lane; n < NT2; n += 32) {
        float v1 = g_p1v[base + n]; int i1 = g_p1i[base + n];
        float v2 = g_p2v[base + n]; int i2 = g_p2i[base + n];
        if (v1 > thr && i1 != Mi) {
            int p = atomicAdd(&s_cnt[w], 1);
            if (p < 127) s_cand[w][p] = i1;
        }
        if (v2 > thr && i2 != Mi && i2 != 0x7fffffff) {
            int p = atomicAdd(&s_cnt[w], 1);
            if (p < 127) s_cand[w][p] = i2;
        }
    }
    __syncwarp();
    int ncand = min(s_cnt[w], 127);

    int besti = Mi;
    if (ncand > 0) {
        // exact fp32 rescore of incumbent + candidates
        float ar[24];
        #pragma unroll
        for (int j = 0; j < 24; j++)
            ar[j] = A[(size_t)tok * KDIM + j * 32 + lane];

        float bestv = -FLT_MAX;
        besti = 0x7fffffff;
        for (int cix = -1; cix < ncand; cix++) {
            int c = (cix < 0) ? Mi : s_cand[w][cix];
            const float* wrow = Wr + (size_t)c * KDIM;
            float s = 0.f;
            #pragma unroll
            for (int j = 0; j < 24; j++)
                s = fmaf(ar[j], wrow[j * 32 + lane], s);
            #pragma unroll
            for (int sh = 16; sh > 0; sh >>= 1)
                s += __shfl_xor_sync(0xffffffffu, s, sh);
            if (lane == 0) {
                float sc = s + br[c] + gum[(size_t)tok * VOC + c];
                if (sc > bestv || (sc == bestv && c < besti)) { bestv = sc; besti = c; }
            }
        }
        besti = __shfl_sync(0xffffffffu, besti, 0);
    }

    // 3) contrib
    if (lane == 0) {
        const int id = ids[tok];
        const int kind = g_mask_kind;
        bool ch;
        if (kind == 1)      ch = ((const int*)mask)[id] != 0;
        else if (kind == 2) ch = ((const float*)mask)[id] != 0.0f;
        else                ch = ((const unsigned char*)mask)[id] != 0;
        g_contrib[tok] = ch ? (1.0f - sim[(size_t)id * VOC + besti]) : 0.0f;
    }
}

// ---------------- final deterministic sum ----------------
__global__ void final_sum(float* __restrict__ out, int out_size) {
    __shared__ float red[1024];
    const int t = threadIdx.x;
    red[t] = g_contrib[t];
    __syncthreads();
    for (int s = 512; s > 0; s >>= 1) {
        if (t < s) red[t] += red[t + s];
        __syncthreads();
    }
    if (t == 0) {
        float L = red[0] * (1.0f / 1024.0f);
        for (int k = 0; k < out_size; k++) out[k] = L;
    }
}

extern "C" void kernel_launch(void* const* d_in, const int* in_sizes, int n_in,
                              void* d_out, int out_size) {
    const float* seq  = (const float*)d_in[0];   // [8,128,768]
    const float* Wr   = (const float*)d_in[1];   // [21128,768]
    const float* br   = (const float*)d_in[2];   // [21128]
    const float* sim  = (const float*)d_in[3];   // [21128,21128]
    const float* gum  = (const float*)d_in[4];   // [8,128,21128]
    const int*   ids  = (const int*)d_in[5];     // [8,128]
    const void*  mask = d_in[6];                 // [21128] bool-ish

    static bool attr_set = false;
    if (!attr_set) {
        cudaFuncSetAttribute(gemm_fp8_top2,
                             cudaFuncAttributeMaxDynamicSharedMemorySize, SM_TOTAL_G);
        attr_set = true;
    }

    convert_fp8<<<2048, 256>>>(seq, Wr, (const unsigned char*)mask);

    dim3 grid(M_TOK / BM, NT2);   // (8, 166); x fastest -> B tile shared in L2
    gemm_fp8_top2<<<grid, 256, SM_TOTAL_G>>>(br, gum);

    rescue_contrib<<<128, 256>>>(seq, Wr, br, gum, sim, ids, mask);
    final_sum<<<1, 1024>>>((float*)d_out, out_size);
}